// round 1
// baseline (speedup 1.0000x reference)
#include <cuda_runtime.h>
#include <math.h>

// Problem constants
#define NUM_HEADS    32
#define HEAD_SIZE    128
#define NUM_KV_HEADS 8
#define GRP          4           // NUM_HEADS / NUM_KV_HEADS
#define BLK_SZ       16
#define MAX_BLOCKS   64
#define MAX_CTX      1024
#define NUM_SEQS     64
#define SCALE        0.08838834764831845f
#define LOG2E        1.4426950408889634f

__global__ __launch_bounds__(256, 4)
void paged_attn_kernel(const float* __restrict__ q_in,
                       const float* __restrict__ knew,
                       const float* __restrict__ vnew,
                       const float* __restrict__ kcache,
                       const float* __restrict__ vcache,
                       const int*   __restrict__ btab,
                       const int*   __restrict__ ctxlen,
                       float*       __restrict__ out)
{
    const int s = blockIdx.x >> 3;     // sequence
    const int h = blockIdx.x & 7;      // kv head
    const int L = ctxlen[s];
    const int nblk = (L + BLK_SZ - 1) / BLK_SZ;
    const int Lp = nblk * BLK_SZ;      // padded length

    const int tid  = threadIdx.x;
    const int lane = tid & 31;
    const int wid  = tid >> 5;         // 8 warps

    __shared__ float sh_q[GRP][HEAD_SIZE];       // 2 KB
    __shared__ float sh_p[GRP][MAX_CTX];         // 16 KB (scores -> probs)
    __shared__ float sh_acc[2][GRP][HEAD_SIZE];  // 4 KB
    __shared__ float sh_inv[GRP];

    // ---- load q for the 4 query heads of this kv head ----
    for (int i = tid; i < GRP * HEAD_SIZE; i += 256) {
        int g = i >> 7, d = i & 127;
        sh_q[g][d] = q_in[(size_t)s * (NUM_HEADS * HEAD_SIZE) + (h * GRP + g) * HEAD_SIZE + d];
    }
    __syncthreads();

    // ---- Phase 1: scores. warp per 16-token block; lane = (token, half-of-dims) ----
    {
        const int tb   = lane & 15;
        const int half = lane >> 4;
        for (int b = wid; b < nblk; b += 8) {
            const int pb = btab[s * MAX_BLOCKS + b];
            const int t  = b * BLK_SZ + tb;

            const float* kb;
            int cs;
            if (t == L - 1) {
                // new token's key comes from the `key` input (not yet in cache)
                kb = knew + (size_t)s * (NUM_KV_HEADS * HEAD_SIZE) + h * HEAD_SIZE + half * 64;
                cs = 8;
            } else {
                // key_cache[pb][h][c][tb][x]; chunk stride 128 floats
                kb = kcache + ((size_t)pb * NUM_KV_HEADS + h) * 2048 + (size_t)half * 1024 + tb * 8;
                cs = 128;
            }

            float acc[GRP] = {0.f, 0.f, 0.f, 0.f};
            #pragma unroll
            for (int j = 0; j < 8; j++) {
                float4 k0 = *(const float4*)(kb + j * cs);
                float4 k1 = *(const float4*)(kb + j * cs + 4);
                int d0 = half * 64 + j * 8;
                #pragma unroll
                for (int g = 0; g < GRP; g++) {
                    float4 qa = *(const float4*)&sh_q[g][d0];
                    float4 qb = *(const float4*)&sh_q[g][d0 + 4];
                    acc[g] += k0.x * qa.x + k0.y * qa.y + k0.z * qa.z + k0.w * qa.w
                            + k1.x * qb.x + k1.y * qb.y + k1.z * qb.z + k1.w * qb.w;
                }
            }
            #pragma unroll
            for (int g = 0; g < GRP; g++)
                acc[g] += __shfl_xor_sync(0xffffffffu, acc[g], 16);

            if (half == 0) {
                #pragma unroll
                for (int g = 0; g < GRP; g++)
                    sh_p[g][t] = (t < L) ? acc[g] * SCALE : -1e30f;
            }
        }
    }
    __syncthreads();

    // ---- Phase 2: softmax (4 warps, one head each). keep 1/sum for epilogue ----
    if (wid < GRP) {
        const int g = wid;
        float m = -1e30f;
        for (int i = lane; i < Lp; i += 32) m = fmaxf(m, sh_p[g][i]);
        #pragma unroll
        for (int o = 16; o > 0; o >>= 1) m = fmaxf(m, __shfl_xor_sync(0xffffffffu, m, o));

        float sum = 0.f;
        for (int i = lane; i < Lp; i += 32) {
            float e = exp2f((sh_p[g][i] - m) * LOG2E);
            sh_p[g][i] = e;
            sum += e;
        }
        #pragma unroll
        for (int o = 16; o > 0; o >>= 1) sum += __shfl_xor_sync(0xffffffffu, sum, o);
        if (lane == 0) sh_inv[g] = 1.f / sum;
    }
    __syncthreads();

    // ---- Phase 3: P @ V. thread owns dim d; two token-halves (even/odd blocks) ----
    {
        const int d  = tid & 127;
        const int th = tid >> 7;
        const float vnd = vnew[(size_t)s * (NUM_KV_HEADS * HEAD_SIZE) + h * HEAD_SIZE + d];

        float acc[GRP] = {0.f, 0.f, 0.f, 0.f};
        for (int b = th; b < nblk; b += 2) {
            const int pb = btab[s * MAX_BLOCKS + b];
            // value_cache[pb][h][d][tb] : token-contiguous
            const float* vb = vcache + ((size_t)pb * NUM_KV_HEADS + h) * 2048 + d * 16;
            const int t0 = b * BLK_SZ;
            #pragma unroll
            for (int j = 0; j < 4; j++) {
                float4 v = *(const float4*)(vb + j * 4);
                const int tb0 = t0 + j * 4;
                const int o = (L - 1) - tb0;    // override new token's value
                if ((unsigned)o < 4u) {
                    if      (o == 0) v.x = vnd;
                    else if (o == 1) v.y = vnd;
                    else if (o == 2) v.z = vnd;
                    else             v.w = vnd;
                }
                #pragma unroll
                for (int g = 0; g < GRP; g++) {
                    acc[g] += v.x * sh_p[g][tb0 + 0];
                    acc[g] += v.y * sh_p[g][tb0 + 1];
                    acc[g] += v.z * sh_p[g][tb0 + 2];
                    acc[g] += v.w * sh_p[g][tb0 + 3];
                }
            }
        }
        #pragma unroll
        for (int g = 0; g < GRP; g++) sh_acc[th][g][d] = acc[g];
    }
    __syncthreads();

    // ---- epilogue: combine halves, apply 1/sum ----
    for (int i = tid; i < GRP * HEAD_SIZE; i += 256) {
        int g = i >> 7, d = i & 127;
        out[(size_t)s * (NUM_HEADS * HEAD_SIZE) + (h * GRP + g) * HEAD_SIZE + d] =
            (sh_acc[0][g][d] + sh_acc[1][g][d]) * sh_inv[g];
    }
}

extern "C" void kernel_launch(void* const* d_in, const int* in_sizes, int n_in,
                              void* d_out, int out_size)
{
    const float* query       = (const float*)d_in[0];
    const float* key         = (const float*)d_in[1];
    const float* value       = (const float*)d_in[2];
    const float* key_cache   = (const float*)d_in[3];
    const float* value_cache = (const float*)d_in[4];
    const int*   block_tab   = (const int*)d_in[5];
    const int*   ctx_lens    = (const int*)d_in[6];
    // d_in[7] = slot_mapping (unused: derived override at t == L-1)
    float* out = (float*)d_out;

    dim3 grid(NUM_SEQS * NUM_KV_HEADS);
    paged_attn_kernel<<<grid, 256>>>(query, key, value, key_cache, value_cache,
                                     block_tab, ctx_lens, out);
}

// round 2
// speedup vs baseline: 1.5999x; 1.5999x over previous
#include <cuda_runtime.h>
#include <math.h>

#define NUM_HEADS    32
#define HEAD_SIZE    128
#define NUM_KV_HEADS 8
#define GRP          4
#define BLK_SZ       16
#define MAX_BLOCKS   64
#define MAX_CTX      1024
#define NUM_SEQS     64
#define SCALE        0.08838834764831845f
#define LOG2E        1.4426950408889634f

#define PART         128                  // tokens per split-K partition
#define MAXP         (MAX_CTX / PART)     // 8
#define PBLK         (PART / BLK_SZ)      // 8 blocks per partition

// split-K scratch (device globals: no allocation allowed)
__device__ float g_po[NUM_SEQS * NUM_KV_HEADS * MAXP * GRP * HEAD_SIZE]; // 8 MB
__device__ float g_pm[NUM_SEQS * NUM_KV_HEADS * MAXP * GRP];
__device__ float g_ps[NUM_SEQS * NUM_KV_HEADS * MAXP * GRP];

__device__ __forceinline__ float4 ldcs4(const float* p) {
    return __ldcs((const float4*)p);
}

__global__ __launch_bounds__(256, 4)
void paged_attn_split(const float* __restrict__ q_in,
                      const float* __restrict__ knew,
                      const float* __restrict__ vnew,
                      const float* __restrict__ kcache,
                      const float* __restrict__ vcache,
                      const int*   __restrict__ btab,
                      const int*   __restrict__ ctxlen)
{
    const int bx = blockIdx.x;
    const int s  = bx >> 6;              // sequence
    const int h  = (bx >> 3) & 7;        // kv head
    const int p  = bx & 7;               // partition

    const int L  = ctxlen[s];
    const int t0 = p * PART;
    if (t0 >= L) return;
    const int t1   = min(L, t0 + PART);
    const int n    = t1 - t0;                       // tokens in this partition
    const int nblk = (n + BLK_SZ - 1) / BLK_SZ;     // <= 8
    const int npad = nblk * BLK_SZ;

    const int tid  = threadIdx.x;
    const int lane = tid & 31;
    const int wid  = tid >> 5;

    __shared__ float sh_q[GRP][HEAD_SIZE];       // 2 KB
    __shared__ float sh_p[GRP][PART];            // 2 KB
    __shared__ float sh_acc[2][GRP][HEAD_SIZE];  // 4 KB
    __shared__ float sh_m[GRP], sh_s[GRP];

    for (int i = tid; i < GRP * HEAD_SIZE; i += 256) {
        int g = i >> 7, d = i & 127;
        sh_q[g][d] = q_in[(size_t)s * (NUM_HEADS * HEAD_SIZE) + (h * GRP + g) * HEAD_SIZE + d];
    }
    __syncthreads();

    // ---- scores: warp wid -> block wid of this partition ----
    if (wid < nblk) {
        const int tb   = lane & 15;
        const int half = lane >> 4;
        const int gb   = p * PBLK + wid;               // block index in sequence
        const int pb   = btab[s * MAX_BLOCKS + gb];    // physical block
        const int t    = t0 + wid * BLK_SZ + tb;       // global token
        const int lt   = wid * BLK_SZ + tb;            // local token

        const float* kb;
        int cs;
        if (t == L - 1) {
            kb = knew + (size_t)s * (NUM_KV_HEADS * HEAD_SIZE) + h * HEAD_SIZE + half * 64;
            cs = 8;
        } else {
            kb = kcache + ((size_t)pb * NUM_KV_HEADS + h) * 2048 + (size_t)half * 1024 + tb * 8;
            cs = 128;
        }

        float acc[GRP] = {0.f, 0.f, 0.f, 0.f};
        #pragma unroll
        for (int j = 0; j < 8; j++) {
            float4 k0 = ldcs4(kb + j * cs);
            float4 k1 = ldcs4(kb + j * cs + 4);
            int d0 = half * 64 + j * 8;
            #pragma unroll
            for (int g = 0; g < GRP; g++) {
                float4 qa = *(const float4*)&sh_q[g][d0];
                float4 qb = *(const float4*)&sh_q[g][d0 + 4];
                acc[g] += k0.x * qa.x + k0.y * qa.y + k0.z * qa.z + k0.w * qa.w
                        + k1.x * qb.x + k1.y * qb.y + k1.z * qb.z + k1.w * qb.w;
            }
        }
        #pragma unroll
        for (int g = 0; g < GRP; g++)
            acc[g] += __shfl_xor_sync(0xffffffffu, acc[g], 16);

        if (half == 0) {
            #pragma unroll
            for (int g = 0; g < GRP; g++)
                sh_p[g][lt] = (lt < n) ? acc[g] * SCALE : -1e30f;
        }
    }
    __syncthreads();

    // ---- local softmax stats (4 warps, one head each) ----
    if (wid < GRP) {
        const int g = wid;
        float m = -1e30f;
        for (int i = lane; i < npad; i += 32) m = fmaxf(m, sh_p[g][i]);
        #pragma unroll
        for (int o = 16; o > 0; o >>= 1) m = fmaxf(m, __shfl_xor_sync(0xffffffffu, m, o));
        float sum = 0.f;
        for (int i = lane; i < npad; i += 32) {
            float e = exp2f((sh_p[g][i] - m) * LOG2E);
            sh_p[g][i] = e;
            sum += e;
        }
        #pragma unroll
        for (int o = 16; o > 0; o >>= 1) sum += __shfl_xor_sync(0xffffffffu, sum, o);
        if (lane == 0) { sh_m[g] = m; sh_s[g] = sum; }
    }
    __syncthreads();

    // ---- partial P@V (unnormalized): thread owns dim d; even/odd blocks ----
    {
        const int d  = tid & 127;
        const int th = tid >> 7;
        const float vnd = vnew[(size_t)s * (NUM_KV_HEADS * HEAD_SIZE) + h * HEAD_SIZE + d];

        float acc[GRP] = {0.f, 0.f, 0.f, 0.f};
        for (int b = th; b < nblk; b += 2) {
            const int pb = btab[s * MAX_BLOCKS + p * PBLK + b];
            const float* vb = vcache + ((size_t)pb * NUM_KV_HEADS + h) * 2048 + d * 16;
            const int lt0 = b * BLK_SZ;
            #pragma unroll
            for (int j = 0; j < 4; j++) {
                float4 v = ldcs4(vb + j * 4);
                const int ltj = lt0 + j * 4;
                const int o = (L - 1) - (t0 + ltj);   // new-token value override
                if ((unsigned)o < 4u) {
                    if      (o == 0) v.x = vnd;
                    else if (o == 1) v.y = vnd;
                    else if (o == 2) v.z = vnd;
                    else             v.w = vnd;
                }
                #pragma unroll
                for (int g = 0; g < GRP; g++) {
                    acc[g] += v.x * sh_p[g][ltj + 0];
                    acc[g] += v.y * sh_p[g][ltj + 1];
                    acc[g] += v.z * sh_p[g][ltj + 2];
                    acc[g] += v.w * sh_p[g][ltj + 3];
                }
            }
        }
        #pragma unroll
        for (int g = 0; g < GRP; g++) sh_acc[th][g][d] = acc[g];
    }
    __syncthreads();

    // ---- write partials ----
    const size_t base = ((size_t)bx) * (GRP * HEAD_SIZE);
    for (int i = tid; i < GRP * HEAD_SIZE; i += 256)
        g_po[base + i] = sh_acc[0][i >> 7][i & 127] + sh_acc[1][i >> 7][i & 127];
    if (tid < GRP) {
        g_pm[(size_t)bx * GRP + tid] = sh_m[tid];
        g_ps[(size_t)bx * GRP + tid] = sh_s[tid];
    }
}

__global__ __launch_bounds__(256)
void paged_attn_combine(const int* __restrict__ ctxlen,
                        float*     __restrict__ out)
{
    const int sh = blockIdx.x;            // s*8 + h
    const int s  = sh >> 3;
    const int L  = ctxlen[s];
    const int np = (L + PART - 1) / PART;

    const int tid = threadIdx.x;

    // per-head combine weights (all threads compute all heads; tiny)
    float w[MAXP][GRP];
    float inv_den[GRP];
    #pragma unroll
    for (int g = 0; g < GRP; g++) {
        float M = -1e30f;
        for (int pp = 0; pp < np; pp++)
            M = fmaxf(M, g_pm[((size_t)sh * MAXP + pp) * GRP + g]);
        float den = 0.f;
        for (int pp = 0; pp < np; pp++) {
            float wv = exp2f((g_pm[((size_t)sh * MAXP + pp) * GRP + g] - M) * LOG2E);
            w[pp][g] = wv;
            den += wv * g_ps[((size_t)sh * MAXP + pp) * GRP + g];
        }
        inv_den[g] = 1.f / den;
    }

    for (int i = tid; i < GRP * HEAD_SIZE; i += 256) {
        const int g = i >> 7, d = i & 127;
        float acc = 0.f;
        for (int pp = 0; pp < np; pp++)
            acc += w[pp][g] * g_po[((size_t)sh * MAXP + pp) * (GRP * HEAD_SIZE) + i];
        const int h = sh & 7;
        out[(size_t)s * (NUM_HEADS * HEAD_SIZE) + (h * GRP + g) * HEAD_SIZE + d] = acc * inv_den[g];
    }
}

extern "C" void kernel_launch(void* const* d_in, const int* in_sizes, int n_in,
                              void* d_out, int out_size)
{
    const float* query       = (const float*)d_in[0];
    const float* key         = (const float*)d_in[1];
    const float* value       = (const float*)d_in[2];
    const float* key_cache   = (const float*)d_in[3];
    const float* value_cache = (const float*)d_in[4];
    const int*   block_tab   = (const int*)d_in[5];
    const int*   ctx_lens    = (const int*)d_in[6];
    float* out = (float*)d_out;

    paged_attn_split<<<NUM_SEQS * NUM_KV_HEADS * MAXP, 256>>>(
        query, key, value, key_cache, value_cache, block_tab, ctx_lens);
    paged_attn_combine<<<NUM_SEQS * NUM_KV_HEADS, 256>>>(ctx_lens, out);
}

// round 3
// speedup vs baseline: 1.6422x; 1.0264x over previous
#include <cuda_runtime.h>
#include <math.h>

#define NUM_HEADS    32
#define HEAD_SIZE    128
#define NUM_KV_HEADS 8
#define GRP          4
#define BLK_SZ       16
#define MAX_BLOCKS   64
#define MAX_CTX      1024
#define NUM_SEQS     64
#define SCALE        0.08838834764831845f
#define LOG2E        1.4426950408889634f

#define PART         128                  // tokens per split-K partition
#define MAXP         (MAX_CTX / PART)     // 8
#define PBLK         (PART / BLK_SZ)      // 8 blocks per partition

// split-K scratch (device globals: no allocation allowed)
__device__ float g_po[NUM_SEQS * NUM_KV_HEADS * MAXP * GRP * HEAD_SIZE]; // 8 MB
__device__ float g_pm[NUM_SEQS * NUM_KV_HEADS * MAXP * GRP];
__device__ float g_ps[NUM_SEQS * NUM_KV_HEADS * MAXP * GRP];
__device__ int   g_cnt[NUM_SEQS * NUM_KV_HEADS];   // zero-init; self-resetting

__device__ __forceinline__ float4 ldcs4(const float* p) {
    return __ldcs((const float4*)p);
}

__global__ __launch_bounds__(256, 4)
void paged_attn_split(const float* __restrict__ q_in,
                      const float* __restrict__ knew,
                      const float* __restrict__ vnew,
                      const float* __restrict__ kcache,
                      const float* __restrict__ vcache,
                      const int*   __restrict__ btab,
                      const int*   __restrict__ ctxlen,
                      float*       __restrict__ out)
{
    const int bx = blockIdx.x;
    const int s  = bx >> 6;              // sequence
    const int h  = (bx >> 3) & 7;        // kv head
    const int p  = bx & 7;               // partition
    const int sh = (s << 3) | h;

    const int L  = ctxlen[s];
    const int t0 = p * PART;
    if (t0 >= L) return;
    const int np   = (L + PART - 1) / PART;         // active partitions for (s,h)
    const int t1   = min(L, t0 + PART);
    const int n    = t1 - t0;                       // tokens in this partition
    const int nblk = (n + BLK_SZ - 1) / BLK_SZ;     // <= 8
    const int npad = nblk * BLK_SZ;

    const int tid  = threadIdx.x;
    const int lane = tid & 31;
    const int wid  = tid >> 5;

    __shared__ float sh_q[GRP][HEAD_SIZE];       // 2 KB
    __shared__ float sh_p[GRP][PART];            // 2 KB
    __shared__ float sh_acc[2][GRP][HEAD_SIZE];  // 4 KB
    __shared__ float sh_m[GRP], sh_s[GRP];
    __shared__ float sh_w[MAXP][GRP];            // combine weights (winner only)
    __shared__ int   sh_win;

    for (int i = tid; i < GRP * HEAD_SIZE; i += 256) {
        int g = i >> 7, d = i & 127;
        sh_q[g][d] = q_in[(size_t)s * (NUM_HEADS * HEAD_SIZE) + (h * GRP + g) * HEAD_SIZE + d];
    }
    __syncthreads();

    // ---- Phase 1: scores. warp per 16-token block ----
    if (wid < nblk) {
        const int tb   = lane & 15;
        const int half = lane >> 4;
        const int pb   = btab[s * MAX_BLOCKS + p * PBLK + wid];
        const int t    = t0 + wid * BLK_SZ + tb;
        const int lt   = wid * BLK_SZ + tb;

        const float* kb;
        int cs;
        if (t == L - 1) {
            kb = knew + (size_t)s * (NUM_KV_HEADS * HEAD_SIZE) + h * HEAD_SIZE + half * 64;
            cs = 8;
        } else {
            kb = kcache + ((size_t)pb * NUM_KV_HEADS + h) * 2048 + (size_t)half * 1024 + tb * 8;
            cs = 128;
        }

        float acc[GRP] = {0.f, 0.f, 0.f, 0.f};
        #pragma unroll
        for (int j = 0; j < 8; j++) {
            float4 k0 = ldcs4(kb + j * cs);
            float4 k1 = ldcs4(kb + j * cs + 4);
            int d0 = half * 64 + j * 8;
            #pragma unroll
            for (int g = 0; g < GRP; g++) {
                float4 qa = *(const float4*)&sh_q[g][d0];
                float4 qb = *(const float4*)&sh_q[g][d0 + 4];
                acc[g] += k0.x * qa.x + k0.y * qa.y + k0.z * qa.z + k0.w * qa.w
                        + k1.x * qb.x + k1.y * qb.y + k1.z * qb.z + k1.w * qb.w;
            }
        }
        #pragma unroll
        for (int g = 0; g < GRP; g++)
            acc[g] += __shfl_xor_sync(0xffffffffu, acc[g], 16);

        if (half == 0) {
            #pragma unroll
            for (int g = 0; g < GRP; g++)
                sh_p[g][lt] = (lt < n) ? acc[g] * SCALE : -1e30f;
        }
    }
    __syncthreads();

    // ---- Phase 2: local softmax stats (4 warps, one head each) ----
    if (wid < GRP) {
        const int g = wid;
        float m = -1e30f;
        for (int i = lane; i < npad; i += 32) m = fmaxf(m, sh_p[g][i]);
        #pragma unroll
        for (int o = 16; o > 0; o >>= 1) m = fmaxf(m, __shfl_xor_sync(0xffffffffu, m, o));
        float sum = 0.f;
        for (int i = lane; i < npad; i += 32) {
            float e = exp2f((sh_p[g][i] - m) * LOG2E);
            sh_p[g][i] = e;
            sum += e;
        }
        #pragma unroll
        for (int o = 16; o > 0; o >>= 1) sum += __shfl_xor_sync(0xffffffffu, sum, o);
        if (lane == 0) { sh_m[g] = m; sh_s[g] = sum; }
    }
    __syncthreads();

    // ---- Phase 3: partial P@V (unnormalized) ----
    {
        const int d  = tid & 127;
        const int th = tid >> 7;
        const float vnd = vnew[(size_t)s * (NUM_KV_HEADS * HEAD_SIZE) + h * HEAD_SIZE + d];

        float acc[GRP] = {0.f, 0.f, 0.f, 0.f};
        for (int b = th; b < nblk; b += 2) {
            const int pb = btab[s * MAX_BLOCKS + p * PBLK + b];
            const float* vb = vcache + ((size_t)pb * NUM_KV_HEADS + h) * 2048 + d * 16;
            const int lt0 = b * BLK_SZ;
            #pragma unroll
            for (int j = 0; j < 4; j++) {
                float4 v = ldcs4(vb + j * 4);
                const int ltj = lt0 + j * 4;
                const int o = (L - 1) - (t0 + ltj);   // new-token value override
                if ((unsigned)o < 4u) {
                    if      (o == 0) v.x = vnd;
                    else if (o == 1) v.y = vnd;
                    else if (o == 2) v.z = vnd;
                    else             v.w = vnd;
                }
                #pragma unroll
                for (int g = 0; g < GRP; g++) {
                    acc[g] += v.x * sh_p[g][ltj + 0];
                    acc[g] += v.y * sh_p[g][ltj + 1];
                    acc[g] += v.z * sh_p[g][ltj + 2];
                    acc[g] += v.w * sh_p[g][ltj + 3];
                }
            }
        }
        #pragma unroll
        for (int g = 0; g < GRP; g++) sh_acc[th][g][d] = acc[g];
    }
    __syncthreads();

    // ---- write partials ----
    const size_t base = ((size_t)bx) * (GRP * HEAD_SIZE);
    for (int i = tid; i < GRP * HEAD_SIZE; i += 256)
        g_po[base + i] = sh_acc[0][i >> 7][i & 127] + sh_acc[1][i >> 7][i & 127];
    if (tid < GRP) {
        g_pm[(size_t)bx * GRP + tid] = sh_m[tid];
        g_ps[(size_t)bx * GRP + tid] = sh_s[tid];
    }

    // ---- fused combine: last CTA for (s,h) finalizes ----
    __threadfence();
    if (tid == 0) {
        int old = atomicAdd(&g_cnt[sh], 1);
        sh_win = (old == np - 1);
        if (sh_win) g_cnt[sh] = 0;   // self-reset for next graph replay
    }
    __syncthreads();
    if (!sh_win) return;
    __threadfence();                  // acquire: see all partitions' partials

    // one warp computes combine weights: lane = g + 4*pp
    if (wid == 0) {
        const int g  = lane & 3;
        const int pp = lane >> 2;
        const bool act = (pp < np);
        const size_t idx = ((size_t)sh * MAXP + pp) * GRP + g;
        float m  = act ? g_pm[idx] : -1e30f;
        float M = m;
        #pragma unroll
        for (int o = 4; o < 32; o <<= 1) M = fmaxf(M, __shfl_xor_sync(0xffffffffu, M, o));
        float w  = act ? exp2f((m - M) * LOG2E) : 0.f;
        float ws = act ? w * g_ps[idx] : 0.f;
        float den = ws;
        #pragma unroll
        for (int o = 4; o < 32; o <<= 1) den += __shfl_xor_sync(0xffffffffu, den, o);
        sh_w[pp][g] = w / den;
    }
    __syncthreads();

    for (int i = tid; i < GRP * HEAD_SIZE; i += 256) {
        const int g = i >> 7, d = i & 127;
        float acc = 0.f;
        for (int pp = 0; pp < np; pp++)
            acc += sh_w[pp][g] * g_po[((size_t)sh * MAXP + pp) * (GRP * HEAD_SIZE) + i];
        out[(size_t)s * (NUM_HEADS * HEAD_SIZE) + (h * GRP + g) * HEAD_SIZE + d] = acc;
    }
}

extern "C" void kernel_launch(void* const* d_in, const int* in_sizes, int n_in,
                              void* d_out, int out_size)
{
    const float* query       = (const float*)d_in[0];
    const float* key         = (const float*)d_in[1];
    const float* value       = (const float*)d_in[2];
    const float* key_cache   = (const float*)d_in[3];
    const float* value_cache = (const float*)d_in[4];
    const int*   block_tab   = (const int*)d_in[5];
    const int*   ctx_lens    = (const int*)d_in[6];
    float* out = (float*)d_out;

    paged_attn_split<<<NUM_SEQS * NUM_KV_HEADS * MAXP, 256>>>(
        query, key, value, key_cache, value_cache, block_tab, ctx_lens, out);
}